// round 11
// baseline (speedup 1.0000x reference)
#include <cuda_runtime.h>
#include <cuda_bf16.h>
#include <cstdint>

// Problem constants (fixed by the reference generator).
#define NN   4096      // nodes
#define BB   2048      // batch
#define LL   128       // latent
#define KK   16        // max fan-in
#define DW   145       // 1 + LL + KK  (weights row length)
#define GKK  129       // 1 + LL       (GEMM K dim)

#define NE      14     // batch elements per CTA (147 CTAs -> one wave)
#define STRIDE  4097   // per-element smem stride: bank = (el + p) mod 32
#define GSZ     16     // nodes per group = compute warps
#define NGRP    (NN / GSZ)          // 256
#define PAD     48     // meta/pre pad rows (prefetch overrun <= +32)

#define STATE_F (NE * STRIDE)       // 57,358 floats of chain state
#define SBUF_F  STATE_F             // 224 floats: partial dots s[j][el]
#define FS_F    (STATE_F + 224 + 2) // 57,584 (byte 230,336, 16B aligned)
#define SMEM_CHAIN_BYTES ((FS_F + 2 * GSZ * 16) * 4)   // 232,384 B <= 232,448

// ---------------------------------------------------------------------------
// Scratch (__device__ globals zero-initialized at load; rows >= NN never
// written -> prefetch overruns read zeros. All writes are idempotent across
// graph replays: same inputs -> same values.)
// ---------------------------------------------------------------------------
__device__ float        g_pre[(NN + PAD) * BB];   // pre[i*BB+b] = bias + z.wz
__device__ unsigned int g_meta[(NN + PAD) * 32];  // 16 parent idx + 16 main-w bits
__device__ float        g_fixw[NN * 16];          // [i][d]=in-window w by offset; [15]=count

// ---------------------------------------------------------------------------
// Kernel 0: probe (shifts ncu's -s 5 capture slot toward chain_kernel).
// ---------------------------------------------------------------------------
__global__ void probe_kernel()
{
    if (threadIdx.x == 0) g_pre[(size_t)(NN + PAD) * BB - 1] = 0.0f;
}

// ---------------------------------------------------------------------------
// Kernel 1: pack meta. Main line gets in-window parent weights ZEROED; those
// weights go to the offset-indexed fixup row instead. parent_mask excludes
// padded slots (parent 0 with mask 0) from the fixup scatter.
// ---------------------------------------------------------------------------
__global__ void pack_meta_kernel(const float* __restrict__ w,
                                 const int*   __restrict__ par,
                                 const float* __restrict__ mask)
{
    const int wid = threadIdx.x >> 5;
    const int k   = threadIdx.x & 31;
    const int i   = blockIdx.x * 8 + wid;
    if (i >= NN) return;

    const int ws = i & ~(GSZ - 1);                 // window start
    bool inw = false;
    if (k < 16) {
        int   p  = par[i * KK + k];
        float wk = w[i * DW + (1 + LL) + k];       // pre-masked (pads = 0)
        inw = (mask[i * KK + k] != 0.0f) && (p >= ws);
        g_meta[i * 32 + k]      = (unsigned)p;
        g_meta[i * 32 + 16 + k] = __float_as_uint(inw ? 0.0f : wk);
        if (inw) g_fixw[i * 16 + (p - ws)] = wk;   // distinct parents -> distinct slot
    }
    unsigned bal = __ballot_sync(0xffffffffu, inw);
    if (k == 0) g_fixw[i * 16 + 15] = (float)__popc(bal);
}

// ---------------------------------------------------------------------------
// Kernel 2: pre[i][b] = sum_{k=0}^{128} w[i][k] * base[b][k],  base=[1, z].
// ---------------------------------------------------------------------------
#define G_PAD 68
__global__ void gemm_pre_kernel(const float* __restrict__ z,
                                const float* __restrict__ w)
{
    extern __shared__ float smg[];
    float* As = smg;
    float* Zs = smg + GKK * G_PAD;

    const int i0 = blockIdx.y * 64;
    const int b0 = blockIdx.x * 64;
    const int tid = threadIdx.x;

    for (int idx = tid; idx < 64 * GKK; idx += 256) {
        int r = idx / GKK, k = idx - r * GKK;
        As[k * G_PAD + r] = w[(i0 + r) * DW + k];
    }
    for (int idx = tid; idx < 64 * GKK; idx += 256) {
        int c = idx / GKK, k = idx - c * GKK;
        Zs[k * G_PAD + c] = (k == 0) ? 1.0f : z[(b0 + c) * LL + (k - 1)];
    }
    __syncthreads();

    const int tx = tid & 15;
    const int ty = tid >> 4;
    const int ri = ty * 4, ci = tx * 4;

    float acc[4][4];
#pragma unroll
    for (int r = 0; r < 4; r++)
#pragma unroll
        for (int c = 0; c < 4; c++) acc[r][c] = 0.0f;

#pragma unroll 3
    for (int k = 0; k < GKK; k++) {
        float4 a  = *reinterpret_cast<const float4*>(&As[k * G_PAD + ri]);
        float4 zc = *reinterpret_cast<const float4*>(&Zs[k * G_PAD + ci]);
        float av[4] = {a.x, a.y, a.z, a.w};
        float zv[4] = {zc.x, zc.y, zc.z, zc.w};
#pragma unroll
        for (int r = 0; r < 4; r++)
#pragma unroll
            for (int c = 0; c < 4; c++)
                acc[r][c] = fmaf(av[r], zv[c], acc[r][c]);
    }

#pragma unroll
    for (int r = 0; r < 4; r++) {
        float4 o = make_float4(acc[r][0], acc[r][1], acc[r][2], acc[r][3]);
        *reinterpret_cast<float4*>(&g_pre[(size_t)(i0 + ri + r) * BB + b0 + ci]) = o;
    }
}

// ---------------------------------------------------------------------------
// Kernel 3: group-parallel chain. 512 threads = 16 compute warps.
// Group g (16 nodes): phase1 — warp j computes node g*16+j's partial dot
// (in-window weights are zero, so uncommitted gathers contribute exactly 0),
// stores it to sbuf; warp 15 prefetches next group's fixup rows into smem.
// Barrier. Warp 0 applies in-window corrections sequentially with node
// values in statically-indexed registers, tanh, commit. Barrier. Repeat.
// No polling; deadlock-free by construction.
// ---------------------------------------------------------------------------
__global__ void __launch_bounds__(512, 1)
chain_kernel(float* __restrict__ out)
{
    extern __shared__ float sm[];
    const int tid  = threadIdx.x;
    const int warp = tid >> 5;
    const int lane = tid & 31;
    const int b0   = blockIdx.x * NE;

    for (int j = tid; j < STATE_F; j += 512) sm[j] = 0.0f;

    const int  elc = lane < 14 ? lane : 13;        // lanes 14-31 mirror el 13
    const bool so  = (lane < 14);
    int b = b0 + elc; if (b >= BB) b = BB - 1;
    float* __restrict__ u = sm + elc * STRIDE;

    // Depth-2 register prefetch of this warp's node stream (i = g*16 + warp).
    const int4*   mp = reinterpret_cast<const int4*>(g_meta);
    const float4* mw = reinterpret_cast<const float4*>(g_meta);
    int4   P[2][4];
    float4 W[2][4];
    float  pre[2];
#pragma unroll
    for (int d = 0; d < 2; d++) {
        const int n = warp + d * GSZ;
#pragma unroll
        for (int q = 0; q < 4; q++) P[d][q] = __ldg(mp + (size_t)n * 8 + q);
#pragma unroll
        for (int q = 0; q < 4; q++) W[d][q] = __ldg(mw + (size_t)n * 8 + 4 + q);
        pre[d] = __ldg(g_pre + (size_t)n * BB + b);
    }

    // fixw prefetch (warp 15): group 0 -> fsmem buffer 0.
    float4* fs4 = reinterpret_cast<float4*>(sm + FS_F);
    const float4* fw4 = reinterpret_cast<const float4*>(g_fixw);
    if (warp == 15) {
#pragma unroll
        for (int q = 0; q < 2; q++)
            fs4[lane + q * 32] = __ldg(fw4 + lane + q * 32);
    }

    float tg0=0,tg1=0,tg2=0,tg3=0,tg4=0,tg5=0,tg6=0,tg7=0,
          tg8=0,tg9=0,tg10=0,tg11=0,tg12=0,tg13=0,tg14=0,tg15=0;

    __syncthreads();

#pragma unroll 1
    for (int g = 0; g < NGRP; g++) {
        const int d = g & 1;

        // ---- phase 1: partial dot for node i = g*16 + warp ----
        {
            int4 p0 = P[d][0], p1 = P[d][1], p2 = P[d][2], p3 = P[d][3];
            float g0  = u[p0.x], g1  = u[p0.y], g2  = u[p0.z], g3  = u[p0.w];
            float g4  = u[p1.x], g5  = u[p1.y], g6  = u[p1.z], g7  = u[p1.w];
            float g8  = u[p2.x], g9  = u[p2.y], g10 = u[p2.z], g11 = u[p2.w];
            float g12 = u[p3.x], g13 = u[p3.y], g14 = u[p3.z], g15 = u[p3.w];

            float a0 = fmaf(g0,  W[d][0].x, pre[d]);
            float a1 = g1  * W[d][0].y;
            float a2 = g2  * W[d][0].z;
            float a3 = g3  * W[d][0].w;
            a0 = fmaf(g4,  W[d][1].x, a0);
            a1 = fmaf(g5,  W[d][1].y, a1);
            a2 = fmaf(g6,  W[d][1].z, a2);
            a3 = fmaf(g7,  W[d][1].w, a3);
            a0 = fmaf(g8,  W[d][2].x, a0);
            a1 = fmaf(g9,  W[d][2].y, a1);
            a2 = fmaf(g10, W[d][2].z, a2);
            a3 = fmaf(g11, W[d][2].w, a3);
            a0 = fmaf(g12, W[d][3].x, a0);
            a1 = fmaf(g13, W[d][3].y, a1);
            a2 = fmaf(g14, W[d][3].z, a2);
            a3 = fmaf(g15, W[d][3].w, a3);
            float s = (a0 + a1) + (a2 + a3);
            if (so) sm[SBUF_F + warp * 14 + elc] = s;
        }

        // refill meta prefetch slot d with node (g+2)*16 + warp (padded rows)
        {
            const int n = (g + 2) * GSZ + warp;
#pragma unroll
            for (int q = 0; q < 4; q++) P[d][q] = __ldg(mp + (size_t)n * 8 + q);
#pragma unroll
            for (int q = 0; q < 4; q++) W[d][q] = __ldg(mw + (size_t)n * 8 + 4 + q);
            pre[d] = __ldg(g_pre + (size_t)n * BB + b);
        }

        // warp 15: prefetch fixw rows for group g+1 into buffer (g+1)&1
        if (warp == 15 && g + 1 < NGRP) {
            float4* dst = fs4 + ((g + 1) & 1) * 64;
            const float4* src = fw4 + (size_t)(g + 1) * 64;
#pragma unroll
            for (int q = 0; q < 2; q++)
                dst[lane + q * 32] = __ldg(src + lane + q * 32);
        }

        __syncthreads();

        // ---- fixup: warp 0 resolves in-window deps for nodes g*16..+15 ----
        if (warp == 0) {
            const float* fs = sm + FS_F + (g & 1) * (GSZ * 16);
            const int ib = g * GSZ;
#define FIX_NODE(J, TGJ)                                                      \
            {                                                                 \
                float s = sm[SBUF_F + (J) * 14 + elc];                        \
                float cnt = fs[(J) * 16 + 15];                                \
                if (cnt != 0.0f) {                                            \
                    float c0 = fs[(J)*16+ 0] * tg0;                           \
                    float c1 = fs[(J)*16+ 1] * tg1;                           \
                    float c2 = fs[(J)*16+ 2] * tg2;                           \
                    float c3 = fs[(J)*16+ 3] * tg3;                           \
                    c0 = fmaf(fs[(J)*16+ 4], tg4,  c0);                       \
                    c1 = fmaf(fs[(J)*16+ 5], tg5,  c1);                       \
                    c2 = fmaf(fs[(J)*16+ 6], tg6,  c2);                       \
                    c3 = fmaf(fs[(J)*16+ 7], tg7,  c3);                       \
                    c0 = fmaf(fs[(J)*16+ 8], tg8,  c0);                       \
                    c1 = fmaf(fs[(J)*16+ 9], tg9,  c1);                       \
                    c2 = fmaf(fs[(J)*16+10], tg10, c2);                       \
                    c3 = fmaf(fs[(J)*16+11], tg11, c3);                       \
                    c0 = fmaf(fs[(J)*16+12], tg12, c0);                       \
                    c1 = fmaf(fs[(J)*16+13], tg13, c1);                       \
                    c2 = fmaf(fs[(J)*16+14], tg14, c2);                       \
                    s += (c0 + c1) + (c2 + c3);                               \
                }                                                             \
                float e, r;                                                   \
                asm("ex2.approx.f32 %0, %1;" : "=f"(e)                        \
                    : "f"(s * 2.885390082f));                                 \
                asm("rcp.approx.f32 %0, %1;" : "=f"(r) : "f"(e + 1.0f));      \
                float t = fmaf(-2.0f, r, 1.0f);                               \
                TGJ = t;                                                      \
                if (so) u[ib + (J)] = t;                                      \
            }
            FIX_NODE(0,  tg0)  FIX_NODE(1,  tg1)  FIX_NODE(2,  tg2)
            FIX_NODE(3,  tg3)  FIX_NODE(4,  tg4)  FIX_NODE(5,  tg5)
            FIX_NODE(6,  tg6)  FIX_NODE(7,  tg7)  FIX_NODE(8,  tg8)
            FIX_NODE(9,  tg9)  FIX_NODE(10, tg10) FIX_NODE(11, tg11)
            FIX_NODE(12, tg12) FIX_NODE(13, tg13) FIX_NODE(14, tg14)
            FIX_NODE(15, tg15)
#undef FIX_NODE
        }
        __syncthreads();
    }

    // Cooperative coalesced dump: SMEM -> out[b*NN + i].
    for (int e = 0; e < NE; e++) {
        const int bo = blockIdx.x * NE + e;
        if (bo >= BB) break;
        const float* __restrict__ us = sm + e * STRIDE;
        for (int j = tid; j < NN; j += 512)
            out[(size_t)bo * NN + j] = us[j];
    }
}

// ---------------------------------------------------------------------------
// Launch. Inputs: z f32[2048,128], weights f32[4096,145],
// parent_mask f32[4096,16], parents i32[4096,16]. Output: f32[2048, 4096].
// ---------------------------------------------------------------------------
extern "C" void kernel_launch(void* const* d_in, const int* in_sizes, int n_in,
                              void* d_out, int out_size)
{
    const float* z       = (const float*)d_in[0];
    const float* weights = (const float*)d_in[1];
    const float* pmask   = (const float*)d_in[2];
    const int*   parents = (const int*)d_in[3];
    float*       out     = (float*)d_out;

    const int gemm_smem  = 2 * GKK * G_PAD * (int)sizeof(float);   // 70,176 B
    const int chain_smem = SMEM_CHAIN_BYTES;                        // 232,384 B

    cudaFuncSetAttribute(gemm_pre_kernel,
                         cudaFuncAttributeMaxDynamicSharedMemorySize, gemm_smem);
    cudaFuncSetAttribute(chain_kernel,
                         cudaFuncAttributeMaxDynamicSharedMemorySize, chain_smem);

    probe_kernel<<<1, 32>>>();

    pack_meta_kernel<<<(NN + 7) / 8, 256>>>(weights, parents, pmask);

    dim3 ggrid(BB / 64, NN / 64);
    gemm_pre_kernel<<<ggrid, 256, gemm_smem>>>(z, weights);

    const int nblocks = (BB + NE - 1) / NE;   // 147
    chain_kernel<<<nblocks, 512, chain_smem>>>(out);
}

// round 12
// speedup vs baseline: 1.3202x; 1.3202x over previous
#include <cuda_runtime.h>
#include <cuda_bf16.h>
#include <cstdint>

// Problem constants (fixed by the reference generator).
#define NN   4096      // nodes
#define BB   2048      // batch
#define LL   128       // latent
#define KK   16        // max fan-in
#define DW   145       // 1 + LL + KK  (weights row length)
#define GKK  129       // 1 + LL       (GEMM K dim)

#define NE      14     // batch elements per CTA (147 CTAs -> one wave)
#define STRIDE  4097   // per-element smem stride: bank = (el + p) mod 32
#define GSZ     16     // nodes per group = compute warps
#define NGRP    (NN / GSZ)          // 256
#define PAD     48     // meta/pre pad rows (prefetch overrun <= +32)

#define STATE_F (NE * STRIDE)       // 57,358 floats of chain state
#define SBUF_F  STATE_F             // 224 floats: partial dots s[J][el]
#define FS_F    (STATE_F + 224 + 2) // 57,584 (byte 230,336, 16B aligned)
#define SMEM_CHAIN_BYTES ((FS_F + 2 * GSZ * 16) * 4)   // 232,384 B <= 232,448

// ---------------------------------------------------------------------------
// Scratch (__device__ globals zero-initialized at load; rows >= NN never
// written -> prefetch overruns read zeros. All writes idempotent across
// graph replays (same inputs -> same values; atomicOr re-ORs same bits).
// ---------------------------------------------------------------------------
__device__ float        g_pre[(NN + PAD) * BB];   // pre[i*BB+b] = bias + z.wz
__device__ unsigned int g_meta[(NN + PAD) * 32];  // 16 parent idx + 16 main-w bits
__device__ float        g_fixw[NN * 16];          // [i][d] = in-window w by offset
__device__ unsigned int g_gmask[NGRP + 8];        // per-group dirty-node bitmask

// ---------------------------------------------------------------------------
// Kernel 0: probe (shifts ncu's -s 5 capture slot toward chain_kernel).
// ---------------------------------------------------------------------------
__global__ void probe_kernel()
{
    if (threadIdx.x == 0) g_pre[(size_t)(NN + PAD) * BB - 1] = 0.0f;
}

// ---------------------------------------------------------------------------
// Kernel 1: pack meta. In-window (same 16-block) live parent weights are
// ZEROED in the main line and scattered to the offset-indexed fixup row;
// the group's dirty bitmask gets bit (i mod 16) if node i has any such dep.
// ---------------------------------------------------------------------------
__global__ void pack_meta_kernel(const float* __restrict__ w,
                                 const int*   __restrict__ par,
                                 const float* __restrict__ mask)
{
    const int wid = threadIdx.x >> 5;
    const int k   = threadIdx.x & 31;
    const int i   = blockIdx.x * 8 + wid;
    if (i >= NN) return;

    const int ws = i & ~(GSZ - 1);                 // window start
    bool inw = false;
    if (k < 16) {
        int   p  = par[i * KK + k];
        float wk = w[i * DW + (1 + LL) + k];       // pre-masked (pads = 0)
        inw = (mask[i * KK + k] != 0.0f) && (p >= ws);
        g_meta[i * 32 + k]      = (unsigned)p;
        g_meta[i * 32 + 16 + k] = __float_as_uint(inw ? 0.0f : wk);
        if (inw) g_fixw[i * 16 + (p - ws)] = wk;   // distinct parents -> distinct slot
    }
    unsigned bal = __ballot_sync(0xffffffffu, inw);
    if (k == 0 && bal)
        atomicOr(&g_gmask[i >> 4], 1u << (i & 15));
}

// ---------------------------------------------------------------------------
// Kernel 2: pre[i][b] = sum_{k=0}^{128} w[i][k] * base[b][k],  base=[1, z].
// ---------------------------------------------------------------------------
#define G_PAD 68
__global__ void gemm_pre_kernel(const float* __restrict__ z,
                                const float* __restrict__ w)
{
    extern __shared__ float smg[];
    float* As = smg;
    float* Zs = smg + GKK * G_PAD;

    const int i0 = blockIdx.y * 64;
    const int b0 = blockIdx.x * 64;
    const int tid = threadIdx.x;

    for (int idx = tid; idx < 64 * GKK; idx += 256) {
        int r = idx / GKK, k = idx - r * GKK;
        As[k * G_PAD + r] = w[(i0 + r) * DW + k];
    }
    for (int idx = tid; idx < 64 * GKK; idx += 256) {
        int c = idx / GKK, k = idx - c * GKK;
        Zs[k * G_PAD + c] = (k == 0) ? 1.0f : z[(b0 + c) * LL + (k - 1)];
    }
    __syncthreads();

    const int tx = tid & 15;
    const int ty = tid >> 4;
    const int ri = ty * 4, ci = tx * 4;

    float acc[4][4];
#pragma unroll
    for (int r = 0; r < 4; r++)
#pragma unroll
        for (int c = 0; c < 4; c++) acc[r][c] = 0.0f;

#pragma unroll 3
    for (int k = 0; k < GKK; k++) {
        float4 a  = *reinterpret_cast<const float4*>(&As[k * G_PAD + ri]);
        float4 zc = *reinterpret_cast<const float4*>(&Zs[k * G_PAD + ci]);
        float av[4] = {a.x, a.y, a.z, a.w};
        float zv[4] = {zc.x, zc.y, zc.z, zc.w};
#pragma unroll
        for (int r = 0; r < 4; r++)
#pragma unroll
            for (int c = 0; c < 4; c++)
                acc[r][c] = fmaf(av[r], zv[c], acc[r][c]);
    }

#pragma unroll
    for (int r = 0; r < 4; r++) {
        float4 o = make_float4(acc[r][0], acc[r][1], acc[r][2], acc[r][3]);
        *reinterpret_cast<float4*>(&g_pre[(size_t)(i0 + ri + r) * BB + b0 + ci]) = o;
    }
}

// ---------------------------------------------------------------------------
// Kernel 3: group-parallel chain with sparse fixup. 512 threads = 16 warps.
// Phase 1 (all 16 warps): warp J computes node g*16+J's dot (in-window
// weights are zero -> safe), speculative tanh, and COMMITS it to u.
// Clean nodes are fully done here, in parallel.
// Phase 2 (warp 0): for each dirty node J (precomputed bitmask, avg ~2.7
// per group), correct s with fixw[J][d]*u[ws+d] (reads u directly; earlier
// dirty nodes already overwritten in order), tanh, overwrite u.
// No per-node registers carried -> clean nodes cost zero fixup work.
// ---------------------------------------------------------------------------
__global__ void __launch_bounds__(512, 1)
chain_kernel(float* __restrict__ out)
{
    extern __shared__ float sm[];
    const int tid  = threadIdx.x;
    const int warp = tid >> 5;
    const int lane = tid & 31;
    const int b0   = blockIdx.x * NE;

    for (int j = tid; j < STATE_F; j += 512) sm[j] = 0.0f;

    const int  elc = lane < 14 ? lane : 13;        // lanes 14-31 mirror el 13
    const bool so  = (lane < 14);
    int b = b0 + elc; if (b >= BB) b = BB - 1;
    float* __restrict__ u = sm + elc * STRIDE;

    // Depth-2 register prefetch of this warp's node stream (i = g*16 + warp).
    const int4*   mp = reinterpret_cast<const int4*>(g_meta);
    const float4* mw = reinterpret_cast<const float4*>(g_meta);
    int4   P[2][4];
    float4 W[2][4];
    float  pre[2];
    unsigned mk[2];                                 // warp 0: dirty masks
#pragma unroll
    for (int d = 0; d < 2; d++) {
        const int n = warp + d * GSZ;
#pragma unroll
        for (int q = 0; q < 4; q++) P[d][q] = __ldg(mp + (size_t)n * 8 + q);
#pragma unroll
        for (int q = 0; q < 4; q++) W[d][q] = __ldg(mw + (size_t)n * 8 + 4 + q);
        pre[d] = __ldg(g_pre + (size_t)n * BB + b);
        mk[d]  = __ldg(&g_gmask[d]);
    }

    // fixw prefetch (warp 15): group 0 -> buffer 0.
    float4* fs4 = reinterpret_cast<float4*>(sm + FS_F);
    const float4* fw4 = reinterpret_cast<const float4*>(g_fixw);
    if (warp == 15) {
#pragma unroll
        for (int q = 0; q < 2; q++)
            fs4[lane + q * 32] = __ldg(fw4 + lane + q * 32);
    }

    __syncthreads();

#pragma unroll 1
    for (int g = 0; g < NGRP; g++) {
        const int d  = g & 1;
        const int ib = g * GSZ;

        // ---- phase 1: dot + speculative tanh + commit, node i = ib + warp
        {
            int4 p0 = P[d][0], p1 = P[d][1], p2 = P[d][2], p3 = P[d][3];
            float g0  = u[p0.x], g1  = u[p0.y], g2  = u[p0.z], g3  = u[p0.w];
            float g4  = u[p1.x], g5  = u[p1.y], g6  = u[p1.z], g7  = u[p1.w];
            float g8  = u[p2.x], g9  = u[p2.y], g10 = u[p2.z], g11 = u[p2.w];
            float g12 = u[p3.x], g13 = u[p3.y], g14 = u[p3.z], g15 = u[p3.w];

            float a0 = fmaf(g0,  W[d][0].x, pre[d]);
            float a1 = g1  * W[d][0].y;
            float a2 = g2  * W[d][0].z;
            float a3 = g3  * W[d][0].w;
            a0 = fmaf(g4,  W[d][1].x, a0);
            a1 = fmaf(g5,  W[d][1].y, a1);
            a2 = fmaf(g6,  W[d][1].z, a2);
            a3 = fmaf(g7,  W[d][1].w, a3);
            a0 = fmaf(g8,  W[d][2].x, a0);
            a1 = fmaf(g9,  W[d][2].y, a1);
            a2 = fmaf(g10, W[d][2].z, a2);
            a3 = fmaf(g11, W[d][2].w, a3);
            a0 = fmaf(g12, W[d][3].x, a0);
            a1 = fmaf(g13, W[d][3].y, a1);
            a2 = fmaf(g14, W[d][3].z, a2);
            a3 = fmaf(g15, W[d][3].w, a3);
            float s = (a0 + a1) + (a2 + a3);
            if (so) sm[SBUF_F + warp * 14 + elc] = s;

            float e, r;
            asm("ex2.approx.f32 %0, %1;" : "=f"(e) : "f"(s * 2.885390082f));
            asm("rcp.approx.f32 %0, %1;" : "=f"(r) : "f"(e + 1.0f));
            float t = fmaf(-2.0f, r, 1.0f);
            if (so) u[ib + warp] = t;              // speculative commit
        }

        // refills (node (g+2)*16 + warp; padded rows beyond NN read zeros)
        const unsigned mcur = mk[d];
        {
            const int n = (g + 2) * GSZ + warp;
#pragma unroll
            for (int q = 0; q < 4; q++) P[d][q] = __ldg(mp + (size_t)n * 8 + q);
#pragma unroll
            for (int q = 0; q < 4; q++) W[d][q] = __ldg(mw + (size_t)n * 8 + 4 + q);
            pre[d] = __ldg(g_pre + (size_t)n * BB + b);
            mk[d]  = __ldg(&g_gmask[g + 2 < NGRP ? g + 2 : NGRP]);  // pad reads 0
        }

        // warp 15: stage fixw rows for group g+1 into buffer (g+1)&1
        if (warp == 15 && g + 1 < NGRP) {
            float4* dst = fs4 + ((g + 1) & 1) * 64;
            const float4* src = fw4 + (size_t)(g + 1) * 64;
#pragma unroll
            for (int q = 0; q < 2; q++)
                dst[lane + q * 32] = __ldg(src + lane + q * 32);
        }

        __syncthreads();

        // ---- phase 2: warp 0 fixes only dirty nodes (bitmask loop) ----
        if (warp == 0) {
            unsigned msk = mcur;
            const float* fsb = sm + FS_F + (g & 1) * (GSZ * 16);
#pragma unroll 1
            while (msk) {
                const int J = __ffs(msk) - 1;
                msk &= msk - 1;
                const float* fr = fsb + J * 16;    // broadcast row
                float s = sm[SBUF_F + J * 14 + elc];

                // corrections: fr[d]=0 for d>=J -> u of later nodes harmless
                float c0 = fr[0]  * u[ib + 0];
                float c1 = fr[1]  * u[ib + 1];
                float c2 = fr[2]  * u[ib + 2];
                float c3 = fr[3]  * u[ib + 3];
                c0 = fmaf(fr[4],  u[ib + 4],  c0);
                c1 = fmaf(fr[5],  u[ib + 5],  c1);
                c2 = fmaf(fr[6],  u[ib + 6],  c2);
                c3 = fmaf(fr[7],  u[ib + 7],  c3);
                c0 = fmaf(fr[8],  u[ib + 8],  c0);
                c1 = fmaf(fr[9],  u[ib + 9],  c1);
                c2 = fmaf(fr[10], u[ib + 10], c2);
                c3 = fmaf(fr[11], u[ib + 11], c3);
                c0 = fmaf(fr[12], u[ib + 12], c0);
                c1 = fmaf(fr[13], u[ib + 13], c1);
                c2 = fmaf(fr[14], u[ib + 14], c2);
                s += (c0 + c1) + (c2 + c3);

                float e, r;
                asm("ex2.approx.f32 %0, %1;" : "=f"(e) : "f"(s * 2.885390082f));
                asm("rcp.approx.f32 %0, %1;" : "=f"(r) : "f"(e + 1.0f));
                float t = fmaf(-2.0f, r, 1.0f);
                if (so) u[ib + J] = t;             // corrected overwrite
            }
        }
        __syncthreads();
    }

    // Cooperative coalesced dump: SMEM -> out[b*NN + i].
    for (int e = 0; e < NE; e++) {
        const int bo = blockIdx.x * NE + e;
        if (bo >= BB) break;
        const float* __restrict__ us = sm + e * STRIDE;
        for (int j = tid; j < NN; j += 512)
            out[(size_t)bo * NN + j] = us[j];
    }
}

// ---------------------------------------------------------------------------
// Launch. Inputs: z f32[2048,128], weights f32[4096,145],
// parent_mask f32[4096,16], parents i32[4096,16]. Output: f32[2048, 4096].
// ---------------------------------------------------------------------------
extern "C" void kernel_launch(void* const* d_in, const int* in_sizes, int n_in,
                              void* d_out, int out_size)
{
    const float* z       = (const float*)d_in[0];
    const float* weights = (const float*)d_in[1];
    const float* pmask   = (const float*)d_in[2];
    const int*   parents = (const int*)d_in[3];
    float*       out     = (float*)d_out;

    const int gemm_smem  = 2 * GKK * G_PAD * (int)sizeof(float);   // 70,176 B
    const int chain_smem = SMEM_CHAIN_BYTES;                        // 232,384 B

    cudaFuncSetAttribute(gemm_pre_kernel,
                         cudaFuncAttributeMaxDynamicSharedMemorySize, gemm_smem);
    cudaFuncSetAttribute(chain_kernel,
                         cudaFuncAttributeMaxDynamicSharedMemorySize, chain_smem);

    probe_kernel<<<1, 32>>>();

    pack_meta_kernel<<<(NN + 7) / 8, 256>>>(weights, parents, pmask);

    dim3 ggrid(BB / 64, NN / 64);
    gemm_pre_kernel<<<ggrid, 256, gemm_smem>>>(z, weights);

    const int nblocks = (BB + NE - 1) / NE;   // 147
    chain_kernel<<<nblocks, 512, chain_smem>>>(out);
}

// round 13
// speedup vs baseline: 1.3969x; 1.0581x over previous
#include <cuda_runtime.h>
#include <cuda_bf16.h>
#include <cstdint>

// Problem constants (fixed by the reference generator).
#define NN   4096      // nodes
#define BB   2048      // batch
#define LL   128       // latent
#define KK   16        // max fan-in
#define DW   145       // 1 + LL + KK  (weights row length)
#define GKK  129       // 1 + LL       (GEMM K dim)

#define NE      14     // batch elements per CTA (147 CTAs -> one wave)
#define STRIDE  4097   // per-element smem stride: bank = (el + p) mod 32

#define STATE_F (NE * STRIDE)                 // 57,358 floats of chain state
#define SMEM_CHAIN_BYTES ((STATE_F + 20) * 4) // + 16 ballot words + pad = 229,512 B

// ---------------------------------------------------------------------------
// Scratch (__device__ globals zero-initialized at load; all writes idempotent
// across graph replays — same inputs produce the same values).
// ---------------------------------------------------------------------------
__device__ float        g_pre[(NN + 8) * BB];   // pre[i*BB+b] = bias + z.wz
__device__ unsigned int g_meta[(NN + 8) * 32];  // 16 parent idx + 16 weight bits
__device__ int          g_pmax[NN + 8];         // max live parent index (-1 for node 0)

// ---------------------------------------------------------------------------
// Kernel 0: probe (shifts ncu's -s 5 capture slot toward chain_kernel).
// ---------------------------------------------------------------------------
__global__ void probe_kernel()
{
    if (threadIdx.x == 0) g_pre[(size_t)(NN + 8) * BB - 1] = 0.0f;
}

// ---------------------------------------------------------------------------
// Kernel 1: pack per-node metadata (128B line: 16 parents + 16 pre-masked
// weights) and pmax[i] = max over live parents (mask!=0), else -1.
// ---------------------------------------------------------------------------
__global__ void pack_meta_kernel(const float* __restrict__ w,
                                 const int*   __restrict__ par,
                                 const float* __restrict__ mask)
{
    const int wid = threadIdx.x >> 5;
    const int k   = threadIdx.x & 31;
    const int i   = blockIdx.x * 8 + wid;
    if (i >= NN) return;

    int p_eff = -1;
    if (k < 16) {
        int p = par[i * KK + k];
        g_meta[i * 32 + k]      = (unsigned)p;
        g_meta[i * 32 + 16 + k] = __float_as_uint(w[i * DW + (1 + LL) + k]);
        if (mask[i * KK + k] != 0.0f) p_eff = p;
    }
    int pm = __reduce_max_sync(0xffffffffu, p_eff);
    if (k == 0) g_pmax[i] = pm;
}

// ---------------------------------------------------------------------------
// Kernel 2: pre[i][b] = sum_{k=0}^{128} w[i][k] * base[b][k],  base=[1, z].
// ---------------------------------------------------------------------------
#define G_PAD 68
__global__ void gemm_pre_kernel(const float* __restrict__ z,
                                const float* __restrict__ w)
{
    extern __shared__ float smg[];
    float* As = smg;
    float* Zs = smg + GKK * G_PAD;

    const int i0 = blockIdx.y * 64;
    const int b0 = blockIdx.x * 64;
    const int tid = threadIdx.x;

    for (int idx = tid; idx < 64 * GKK; idx += 256) {
        int r = idx / GKK, k = idx - r * GKK;
        As[k * G_PAD + r] = w[(i0 + r) * DW + k];
    }
    for (int idx = tid; idx < 64 * GKK; idx += 256) {
        int c = idx / GKK, k = idx - c * GKK;
        Zs[k * G_PAD + c] = (k == 0) ? 1.0f : z[(b0 + c) * LL + (k - 1)];
    }
    __syncthreads();

    const int tx = tid & 15;
    const int ty = tid >> 4;
    const int ri = ty * 4, ci = tx * 4;

    float acc[4][4];
#pragma unroll
    for (int r = 0; r < 4; r++)
#pragma unroll
        for (int c = 0; c < 4; c++) acc[r][c] = 0.0f;

#pragma unroll 3
    for (int k = 0; k < GKK; k++) {
        float4 a  = *reinterpret_cast<const float4*>(&As[k * G_PAD + ri]);
        float4 zc = *reinterpret_cast<const float4*>(&Zs[k * G_PAD + ci]);
        float av[4] = {a.x, a.y, a.z, a.w};
        float zv[4] = {zc.x, zc.y, zc.z, zc.w};
#pragma unroll
        for (int r = 0; r < 4; r++)
#pragma unroll
            for (int c = 0; c < 4; c++)
                acc[r][c] = fmaf(av[r], zv[c], acc[r][c]);
    }

#pragma unroll
    for (int r = 0; r < 4; r++) {
        float4 o = make_float4(acc[r][0], acc[r][1], acc[r][2], acc[r][3]);
        *reinterpret_cast<float4*>(&g_pre[(size_t)(i0 + ri + r) * BB + b0 + ci]) = o;
    }
}

// ---------------------------------------------------------------------------
// Node load/compute helpers for the level-scheduled chain.
// ---------------------------------------------------------------------------
__device__ __forceinline__ void load_node(int n, int b,
                                          int4 P[4], float4 W[4], float& pre)
{
    const int4*   mp = reinterpret_cast<const int4*>(g_meta);
    const float4* mw = reinterpret_cast<const float4*>(g_meta);
#pragma unroll
    for (int q = 0; q < 4; q++) P[q] = __ldg(mp + (size_t)n * 8 + q);
#pragma unroll
    for (int q = 0; q < 4; q++) W[q] = __ldg(mw + (size_t)n * 8 + 4 + q);
    pre = __ldg(g_pre + (size_t)n * BB + b);
}

__device__ __forceinline__ void compute_node(int n, float* __restrict__ u,
                                             bool so, const int4 P[4],
                                             const float4 W[4], float pre)
{
    float g0  = u[P[0].x], g1  = u[P[0].y], g2  = u[P[0].z], g3  = u[P[0].w];
    float g4  = u[P[1].x], g5  = u[P[1].y], g6  = u[P[1].z], g7  = u[P[1].w];
    float g8  = u[P[2].x], g9  = u[P[2].y], g10 = u[P[2].z], g11 = u[P[2].w];
    float g12 = u[P[3].x], g13 = u[P[3].y], g14 = u[P[3].z], g15 = u[P[3].w];

    float a0 = fmaf(g0,  W[0].x, pre);
    float a1 = g1  * W[0].y;
    float a2 = g2  * W[0].z;
    float a3 = g3  * W[0].w;
    a0 = fmaf(g4,  W[1].x, a0);
    a1 = fmaf(g5,  W[1].y, a1);
    a2 = fmaf(g6,  W[1].z, a2);
    a3 = fmaf(g7,  W[1].w, a3);
    a0 = fmaf(g8,  W[2].x, a0);
    a1 = fmaf(g9,  W[2].y, a1);
    a2 = fmaf(g10, W[2].z, a2);
    a3 = fmaf(g11, W[2].w, a3);
    a0 = fmaf(g12, W[3].x, a0);
    a1 = fmaf(g13, W[3].y, a1);
    a2 = fmaf(g14, W[3].z, a2);
    a3 = fmaf(g15, W[3].w, a3);
    float s = (a0 + a1) + (a2 + a3);

    float e, r;
    asm("ex2.approx.f32 %0, %1;" : "=f"(e) : "f"(s * 2.885390082f));
    asm("rcp.approx.f32 %0, %1;" : "=f"(r) : "f"(e + 1.0f));
    float t = fmaf(-2.0f, r, 1.0f);
    if (so) u[n] = t;
}

// ---------------------------------------------------------------------------
// Kernel 3: level-scheduled chain. 512 threads = 16 compute warps.
// Loop: scan window [a, a+512) of pmax; first j with pmax[j] >= a defines
// the level [a, c) — every node in it has ALL parents < a (committed), so
// the 16 warps compute the whole level in parallel (warp w: nodes a+w,
// a+w+16, ...), then one barrier. Progress guaranteed (pmax[a] < a always);
// barriers uniform (c derived identically from shared ballots); no atomics,
// no polling, no serial segment. ~140-220 levels total.
// ---------------------------------------------------------------------------
__global__ void __launch_bounds__(512, 1)
chain_kernel(float* __restrict__ out)
{
    extern __shared__ float sm[];
    unsigned* smb = reinterpret_cast<unsigned*>(sm + STATE_F);  // 16 ballots
    const int tid  = threadIdx.x;
    const int warp = tid >> 5;
    const int lane = tid & 31;

    for (int j = tid; j < STATE_F; j += 512) sm[j] = 0.0f;

    const int  elc = lane < 14 ? lane : 13;        // lanes 14-31 mirror el 13
    const bool so  = (lane < 14);
    int b = blockIdx.x * NE + elc; if (b >= BB) b = BB - 1;
    float* __restrict__ u = sm + elc * STRIDE;

    __syncthreads();

    int a = 0;
#pragma unroll 1
    while (a < NN) {
        // ---- boundary scan: first j in [a, a+512) with pmax[j] >= a ----
        const int my = a + tid;
        const int v  = (my < NN) ? __ldg(g_pmax + my) : 0x7fffffff;
        unsigned bal = __ballot_sync(0xffffffffu, v >= a);
        if (lane == 0) smb[warp] = bal;
        __syncthreads();

        int fb = 512;
#pragma unroll
        for (int w2 = 15; w2 >= 0; w2--) {
            unsigned x = smb[w2];
            if (x) fb = (w2 << 5) + __ffs(x) - 1;
        }
        const int c = a + fb;                      // uniform across all threads

        // ---- compute level [a, c): warp w owns a+w, a+w+16, ... ----
        const int n0 = a + warp;
        const int n1 = n0 + 16;
        int4 Pa[4], Pb[4];
        float4 Wa[4], Wb[4];
        float pa, pb;
        const bool h0 = (n0 < c), h1 = (n1 < c);
        if (h0) load_node(n0, b, Pa, Wa, pa);      // both LDG batches issued
        if (h1) load_node(n1, b, Pb, Wb, pb);      //   before any compute
        if (h0) compute_node(n0, u, so, Pa, Wa, pa);
        if (h1) compute_node(n1, u, so, Pb, Wb, pb);
#pragma unroll 1
        for (int n = n0 + 32; n < c; n += 16) {    // rare large-level tail
            load_node(n, b, Pa, Wa, pa);
            compute_node(n, u, so, Pa, Wa, pa);
        }

        __syncthreads();                           // level committed
        a = c;
    }

    // Cooperative coalesced dump: SMEM -> out[b*NN + i].
    for (int e = 0; e < NE; e++) {
        const int bo = blockIdx.x * NE + e;
        if (bo >= BB) break;
        const float* __restrict__ us = sm + e * STRIDE;
        for (int j = tid; j < NN; j += 512)
            out[(size_t)bo * NN + j] = us[j];
    }
}

// ---------------------------------------------------------------------------
// Launch. Inputs: z f32[2048,128], weights f32[4096,145],
// parent_mask f32[4096,16], parents i32[4096,16]. Output: f32[2048, 4096].
// ---------------------------------------------------------------------------
extern "C" void kernel_launch(void* const* d_in, const int* in_sizes, int n_in,
                              void* d_out, int out_size)
{
    const float* z       = (const float*)d_in[0];
    const float* weights = (const float*)d_in[1];
    const float* pmask   = (const float*)d_in[2];
    const int*   parents = (const int*)d_in[3];
    float*       out     = (float*)d_out;

    const int gemm_smem  = 2 * GKK * G_PAD * (int)sizeof(float);   // 70,176 B
    const int chain_smem = SMEM_CHAIN_BYTES;                        // 229,512 B

    cudaFuncSetAttribute(gemm_pre_kernel,
                         cudaFuncAttributeMaxDynamicSharedMemorySize, gemm_smem);
    cudaFuncSetAttribute(chain_kernel,
                         cudaFuncAttributeMaxDynamicSharedMemorySize, chain_smem);

    probe_kernel<<<1, 32>>>();

    pack_meta_kernel<<<(NN + 7) / 8, 256>>>(weights, parents, pmask);

    dim3 ggrid(BB / 64, NN / 64);
    gemm_pre_kernel<<<ggrid, 256, gemm_smem>>>(z, weights);

    const int nblocks = (BB + NE - 1) / NE;   // 147
    chain_kernel<<<nblocks, 512, chain_smem>>>(out);
}